// round 4
// baseline (speedup 1.0000x reference)
#include <cuda_runtime.h>
#include <cstdint>

#define NB   64
#define NPG  1024
#define NFEA 8
#define MIN_DIST 2.9f
#define T2CLAMP 1e-12f

#define JCHUNKS 16
#define CHUNK_J (NPG / JCHUNKS)   // 64
#define CTHREADS 256

typedef unsigned long long u64;

// per-block / per-batch partial slots (fully overwritten every launch — no zeroing needed)
__device__ float g_coll[JCHUNKS * NB];      // 1024 collapse block sums
__device__ float g_sb[NB][8];               // per batch: rsum, esum, ecnt, vol, field

// ---------------- packed f32x2 helpers ----------------
__device__ __forceinline__ u64 fma2(u64 a, u64 b, u64 c) {
    u64 d; asm("fma.rn.f32x2 %0,%1,%2,%3;" : "=l"(d) : "l"(a), "l"(b), "l"(c)); return d;
}
__device__ __forceinline__ u64 add2(u64 a, u64 b) {
    u64 d; asm("add.rn.f32x2 %0,%1,%2;" : "=l"(d) : "l"(a), "l"(b)); return d;
}
__device__ __forceinline__ u64 pack2(float lo, float hi) {
    u64 r; asm("mov.b64 %0,{%1,%2};" : "=l"(r) : "f"(lo), "f"(hi)); return r;
}
__device__ __forceinline__ void unpack2(float& lo, float& hi, u64 v) {
    asm("mov.b64 {%0,%1},%2;" : "=f"(lo), "=f"(hi) : "l"(v));
}
__device__ __forceinline__ u64 bcast2(float f) {
    u64 r; asm("mov.b64 %0,{%1,%1};" : "=l"(r) : "f"(f)); return r;
}
__device__ __forceinline__ float sqrt_approx(float x) {
    float d; asm("sqrt.approx.f32 %0,%1;" : "=f"(d) : "f"(x)); return d;
}

// ---------------- float block reduction (256 threads) ----------------
template <int MODE>   // 0 sum, 1 min, 2 max
__device__ __forceinline__ float blockReduce(float v, float* sbuf) {
    const int lane = threadIdx.x & 31;
    const int wid  = threadIdx.x >> 5;
#pragma unroll
    for (int o = 16; o; o >>= 1) {
        float u = __shfl_down_sync(0xffffffffu, v, o);
        v = (MODE == 0) ? (v + u) : (MODE == 1 ? fminf(v, u) : fmaxf(v, u));
    }
    if (lane == 0) sbuf[wid] = v;
    __syncthreads();
    if (wid == 0) {
        v = (lane < 8) ? sbuf[lane] : (MODE == 0 ? 0.0f : sbuf[0]);
#pragma unroll
        for (int o = 16; o; o >>= 1) {
            float u = __shfl_down_sync(0xffffffffu, v, o);
            v = (MODE == 0) ? (v + u) : (MODE == 1 ? fminf(v, u) : fmaxf(v, u));
        }
        if (lane == 0) sbuf[0] = v;
    }
    __syncthreads();
    float r = sbuf[0];
    __syncthreads();
    return r;
}

// ---------------- double sum block reduction (256 threads) ----------------
__device__ __forceinline__ double blockReduceD(double v, double* sbuf) {
    const int lane = threadIdx.x & 31;
    const int wid  = threadIdx.x >> 5;
#pragma unroll
    for (int o = 16; o; o >>= 1) v += __shfl_down_sync(0xffffffffu, v, o);
    if (lane == 0) sbuf[wid] = v;
    __syncthreads();
    if (wid == 0) {
        v = (lane < 8) ? sbuf[lane] : 0.0;
#pragma unroll
        for (int o = 16; o; o >>= 1) v += __shfl_down_sync(0xffffffffu, v, o);
        if (lane == 0) sbuf[0] = v;
    }
    __syncthreads();
    double r = sbuf[0];
    __syncthreads();
    return r;
}

// ---------------- stats kernel: recon, volume, electrode, field ----------------
__global__ __launch_bounds__(256) void k_stats(
    const float* __restrict__ pred,
    const float* __restrict__ tru,
    const float* __restrict__ org,
    const float* __restrict__ nfeat)
{
    __shared__ float sbuf[8];
    const int b = blockIdx.x;
    const int t = threadIdx.x;

    float px[4], py[4], pz[4], ox[4], oy[4], oz[4];
    float rsum = 0.0f;

#pragma unroll
    for (int k = 0; k < 4; k++) {
        const int idx = b * NPG + t + k * 256;
        const float* pp = pred + 3 * idx;
        const float* tt = tru  + 3 * idx;
        const float* oo = org  + 3 * idx;
        px[k] = pp[0]; py[k] = pp[1]; pz[k] = pp[2];
        const float dx = px[k] - tt[0];
        const float dy = py[k] - tt[1];
        const float dz = pz[k] - tt[2];
        rsum += dx * dx + dy * dy + dz * dz;
        ox[k] = oo[0]; oy[k] = oo[1]; oz[k] = oo[2];
    }

    float pmnx = fminf(fminf(px[0], px[1]), fminf(px[2], px[3]));
    float pmxx = fmaxf(fmaxf(px[0], px[1]), fmaxf(px[2], px[3]));
    float pmny = fminf(fminf(py[0], py[1]), fminf(py[2], py[3]));
    float pmxy = fmaxf(fmaxf(py[0], py[1]), fmaxf(py[2], py[3]));
    float pmnz = fminf(fminf(pz[0], pz[1]), fminf(pz[2], pz[3]));
    float pmxz = fmaxf(fmaxf(pz[0], pz[1]), fmaxf(pz[2], pz[3]));
    float omnx = fminf(fminf(ox[0], ox[1]), fminf(ox[2], ox[3]));
    float omxx = fmaxf(fmaxf(ox[0], ox[1]), fmaxf(ox[2], ox[3]));
    float omny = fminf(fminf(oy[0], oy[1]), fminf(oy[2], oy[3]));
    float omxy = fmaxf(fmaxf(oy[0], oy[1]), fmaxf(oy[2], oy[3]));
    float omnz = fminf(fminf(oz[0], oz[1]), fminf(oz[2], oz[3]));
    float omxz = fmaxf(fmaxf(oz[0], oz[1]), fmaxf(oz[2], oz[3]));
    float szp  = pz[0] + pz[1] + pz[2] + pz[3];

    const float PMNX = blockReduce<1>(pmnx, sbuf);
    const float PMXX = blockReduce<2>(pmxx, sbuf);
    const float PMNY = blockReduce<1>(pmny, sbuf);
    const float PMXY = blockReduce<2>(pmxy, sbuf);
    const float PMNZ = blockReduce<1>(pmnz, sbuf);
    const float PMXZ = blockReduce<2>(pmxz, sbuf);
    const float OMNX = blockReduce<1>(omnx, sbuf);
    const float OMXX = blockReduce<2>(omxx, sbuf);
    const float OMNY = blockReduce<1>(omny, sbuf);
    const float OMXY = blockReduce<2>(omxy, sbuf);
    const float OMNZ = blockReduce<1>(omnz, sbuf);
    const float OMXZ = blockReduce<2>(omxz, sbuf);
    const float SZP  = blockReduce<0>(szp,  sbuf);
    const float RS   = blockReduce<0>(rsum, sbuf);

    const float zr   = __fsub_rn(OMXZ, OMNZ);
    const float thlo = __fadd_rn(OMNZ, __fmul_rn(0.15f, zr));
    const float thhi = __fsub_rn(OMXZ, __fmul_rn(0.15f, zr));

    float esum = 0.0f, ecnt = 0.0f;
#pragma unroll
    for (int k = 0; k < 4; k++) {
        const bool m = (oz[k] <= thlo) || (oz[k] >= thhi);
        if (m) {
            const float dx = px[k] - ox[k];
            const float dy = py[k] - oy[k];
            const float dz = pz[k] - oz[k];
            esum += dx * dx + dy * dy + dz * dz;
            ecnt += 1.0f;
        }
    }
    const float ES = blockReduce<0>(esum, sbuf);
    const float EC = blockReduce<0>(ecnt, sbuf);

    if (t == 0) {
        const float pdx = PMXX - PMNX, pdy = PMXY - PMNY, pdz = PMXZ - PMNZ;
        const float odx = OMXX - OMNX, ody = OMXY - OMNY, odz = OMXZ - OMNZ;
        const float rx = (pdx - odx) / (odx + 1e-8f);
        const float ry = (pdy - ody) / (ody + 1e-8f);
        const float rz = (pdz - odz) / (odz + 1e-8f);
        const float xy_pen = fmaxf(rx - 0.02f, 0.0f) + fmaxf(ry - 0.02f, 0.0f);
        const float z_pen  = fmaxf(rz, 0.0f);

        const float zcom  = SZP * (1.0f / 1024.0f);
        const float znorm = (zcom - PMNZ) / ((PMXZ - PMNZ) + 1e-8f);
        const float v = nfeat[(size_t)b * NPG * NFEA + (NFEA - 3)];
        const float target = (v > 0.0f) ? 0.6f : 0.4f;
        const float dvz = znorm - target;
        const float contrib = (fabsf(v) >= 1e-6f) ? dvz * dvz : 0.0f;

        g_sb[b][0] = RS;
        g_sb[b][1] = ES;
        g_sb[b][2] = EC;
        g_sb[b][3] = xy_pen + 2.0f * z_pen;
        g_sb[b][4] = contrib;
    }
}

// ---------------- collapse kernel (packed f32x2) ----------------
// grid = (JCHUNKS, NB). Block: all 1024 rows x CHUNK_J cols of one batch.
// 256 threads, 4 rows/thread as 2 packed f32x2 groups; j chunk in SMEM
// pre-broadcast: per point 4x u64 = {(x,x),(y,y),(z,z),(s,s)}.
__global__ __launch_bounds__(CTHREADS) void k_collapse(const float* __restrict__ pred)
{
    __shared__ u64 sj[CHUNK_J * 4];
    __shared__ float sred[8];
    const int b  = blockIdx.y;
    const int jc = blockIdx.x;
    const int t  = threadIdx.x;
    const int jbase = jc * CHUNK_J;

    if (t < CHUNK_J) {
        const int j = jbase + t;
        const float* p = pred + 3 * (size_t)(b * NPG + j);
        const float x = p[0], y = p[1], z = p[2];
        const float s = fmaf(x, x, fmaf(y, y, z * z));
        sj[t * 4 + 0] = bcast2(x);
        sj[t * 4 + 1] = bcast2(y);
        sj[t * 4 + 2] = bcast2(z);
        sj[t * 4 + 3] = bcast2(s);
    }

    // row registers: m2* = -2 * coord (folds the -2*dot into the fma chain)
    float m2x[4], m2y[4], m2z[4], si[4];
#pragma unroll
    for (int k = 0; k < 4; k++) {
        const int i = t + k * 256;
        const float* p = pred + 3 * (size_t)(b * NPG + i);
        const float x = p[0], y = p[1], z = p[2];
        si[k]  = fmaf(x, x, fmaf(y, y, z * z));
        m2x[k] = -2.0f * x;
        m2y[k] = -2.0f * y;
        m2z[k] = -2.0f * z;
    }
    const u64 X01 = pack2(m2x[0], m2x[1]), X23 = pack2(m2x[2], m2x[3]);
    const u64 Y01 = pack2(m2y[0], m2y[1]), Y23 = pack2(m2y[2], m2y[3]);
    const u64 Z01 = pack2(m2z[0], m2z[1]), Z23 = pack2(m2z[2], m2z[3]);
    const u64 S01 = pack2(si[0],  si[1]),  S23 = pack2(si[2],  si[3]);
    __syncthreads();

    float acc0 = 0.0f, acc1 = 0.0f, acc2v = 0.0f, acc3 = 0.0f;

#pragma unroll 4
    for (int jj = 0; jj < CHUNK_J; jj++) {
        const u64 qx2 = sj[jj * 4 + 0];
        const u64 qy2 = sj[jj * 4 + 1];
        const u64 qz2 = sj[jj * 4 + 2];
        const u64 qw2 = sj[jj * 4 + 3];

        // group 0: rows k=0,1
        {
            const u64 d2p = fma2(X01, qx2, fma2(Y01, qy2, fma2(Z01, qz2, add2(S01, qw2))));
            float a, c; unpack2(a, c, d2p);
            a = fmaxf(a, T2CLAMP);  c = fmaxf(c, T2CLAMP);
            const float da = sqrt_approx(a), dc = sqrt_approx(c);
            float ea = MIN_DIST - da, ec = MIN_DIST - dc;
            ea = fmaxf(ea, 0.0f);   ec = fmaxf(ec, 0.0f);
            acc0 = fmaf(ea, ea, acc0);
            acc1 = fmaf(ec, ec, acc1);
        }
        // group 1: rows k=2,3
        {
            const u64 d2p = fma2(X23, qx2, fma2(Y23, qy2, fma2(Z23, qz2, add2(S23, qw2))));
            float a, c; unpack2(a, c, d2p);
            a = fmaxf(a, T2CLAMP);  c = fmaxf(c, T2CLAMP);
            const float da = sqrt_approx(a), dc = sqrt_approx(c);
            float ea = MIN_DIST - da, ec = MIN_DIST - dc;
            ea = fmaxf(ea, 0.0f);   ec = fmaxf(ec, 0.0f);
            acc2v = fmaf(ea, ea, acc2v);
            acc3  = fmaf(ec, ec, acc3);
        }
    }

    float acc = (acc0 + acc1) + (acc2v + acc3);

    // Subtract the self-pair if this block's j-window contains row i = t + 256k.
    // Scalar fmaf chain with identical operands/order as the packed halves
    // (f32x2 halves round identically to scalar FFMA) -> exact cancellation.
#pragma unroll
    for (int k = 0; k < 4; k++) {
        const int i  = t + k * 256;
        const int jj = i - jbase;
        if (jj >= 0 && jj < CHUNK_J) {
            float qx, qy, qz, qw, dummy;
            unpack2(qx, dummy, sj[jj * 4 + 0]);
            unpack2(qy, dummy, sj[jj * 4 + 1]);
            unpack2(qz, dummy, sj[jj * 4 + 2]);
            unpack2(qw, dummy, sj[jj * 4 + 3]);
            float d2 = fmaf(m2x[k], qx, fmaf(m2y[k], qy, fmaf(m2z[k], qz, si[k] + qw)));
            d2 = fmaxf(d2, T2CLAMP);
            const float d = sqrt_approx(d2);
            float e = MIN_DIST - d;
            e = fmaxf(e, 0.0f);
            acc = fmaf(-e, e, acc);
        }
    }

    const float S = blockReduce<0>(acc, sred);
    if (t == 0) g_coll[b * JCHUNKS + jc] = S;
}

// ---------------- finalize: deterministic double reduction of slots ----------------
__global__ __launch_bounds__(256) void k_finalize(float* __restrict__ out, int out_size)
{
    __shared__ double dbuf[8];
    const int t = threadIdx.x;

    double cs = 0.0;
#pragma unroll
    for (int k = 0; k < 4; k++) cs += (double)g_coll[t + k * 256];
    const double COLL = blockReduceD(cs, dbuf);

    double r = 0.0, e = 0.0, c = 0.0, vo = 0.0, f = 0.0;
    if (t < NB) {
        r  = (double)g_sb[t][0];
        e  = (double)g_sb[t][1];
        c  = (double)g_sb[t][2];
        vo = (double)g_sb[t][3];
        f  = (double)g_sb[t][4];
    }
    const double RSUM = blockReduceD(r,  dbuf);
    const double ESUM = blockReduceD(e,  dbuf);
    const double ECNT = blockReduceD(c,  dbuf);
    const double VSUM = blockReduceD(vo, dbuf);
    const double FSUM = blockReduceD(f,  dbuf);

    if (t == 0) {
        const double recon  = RSUM / (double)(NB * NPG * 3);
        const double volume = VSUM / (double)NB;
        const double elec   = ESUM / (ECNT * 3.0);
        const double coll   = COLL / ((double)NB * (double)NPG * (double)(NPG - 1));
        const double field  = FSUM / (double)NB;
        const double total  = 1.0 * recon + 10.0 * volume + 50.0 * elec
                            + 5.0 * coll + 2.0 * field;
        double vals[6] = { total, recon, volume, elec, coll, field };
        for (int i = 0; i < 6 && i < out_size; i++) out[i] = (float)vals[i];
    }
}

extern "C" void kernel_launch(void* const* d_in, const int* in_sizes, int n_in,
                              void* d_out, int out_size)
{
    // Resolve inputs by element count (robust to metadata ordering).
    int coord_idx[3]; int n_coord = 0;
    int nf_idx = -1, bv_idx = -1;
    for (int i = 0; i < n_in; i++) {
        if (in_sizes[i] == NB * NPG * 3) { if (n_coord < 3) coord_idx[n_coord] = i; n_coord++; }
        else if (in_sizes[i] == NB * NPG * NFEA) nf_idx = i;
        else if (in_sizes[i] == NB * NPG) bv_idx = i;
    }

    const float *pred, *tru, *org, *nf;
    if (n_coord == 3 && nf_idx >= 0) {
        if (bv_idx >= 0 && bv_idx < coord_idx[0]) {
            org  = (const float*)d_in[coord_idx[0]];
            pred = (const float*)d_in[coord_idx[1]];
            tru  = (const float*)d_in[coord_idx[2]];
        } else {
            pred = (const float*)d_in[coord_idx[0]];
            tru  = (const float*)d_in[coord_idx[1]];
            org  = (const float*)d_in[coord_idx[2]];
        }
        nf = (const float*)d_in[nf_idx];
    } else {
        pred = (const float*)d_in[0];
        tru  = (const float*)d_in[1];
        org  = (const float*)d_in[2];
        nf   = (const float*)d_in[3];
    }

    float* out = (float*)d_out;

    k_stats<<<NB, 256>>>(pred, tru, org, nf);
    k_collapse<<<dim3(JCHUNKS, NB), CTHREADS>>>(pred);
    k_finalize<<<1, 256>>>(out, out_size);
}

// round 5
// speedup vs baseline: 1.0996x; 1.0996x over previous
#include <cuda_runtime.h>
#include <cstdint>

#define NB   64
#define NPG  1024
#define NFEA 8
#define MIN_DIST 2.9f
#define T2CLAMP 1e-12f

#define JCHUNKS 16
#define CHUNK_J (NPG / JCHUNKS)   // 64
#define CTHREADS 256
#define NBLOCKS ((JCHUNKS + 1) * NB)   // 1088

// partial slots — fully overwritten every launch
__device__ float g_coll[JCHUNKS * NB];   // collapse block sums
__device__ float g_sb[NB][8];            // per batch: rsum, esum, ecnt, vol, field
__device__ unsigned int g_done = 0;      // last-block counter (reset by last block)

// ---------------- warp reduce helpers ----------------
__device__ __forceinline__ float wredSum(float v) {
#pragma unroll
    for (int o = 16; o; o >>= 1) v += __shfl_down_sync(0xffffffffu, v, o);
    return v;
}
__device__ __forceinline__ float wredMin(float v) {
#pragma unroll
    for (int o = 16; o; o >>= 1) v = fminf(v, __shfl_down_sync(0xffffffffu, v, o));
    return v;
}
__device__ __forceinline__ float wredMax(float v) {
#pragma unroll
    for (int o = 16; o; o >>= 1) v = fmaxf(v, __shfl_down_sync(0xffffffffu, v, o));
    return v;
}

// float block sum (256 threads)
__device__ __forceinline__ float blockSum(float v, float* sbuf) {
    const int lane = threadIdx.x & 31;
    const int wid  = threadIdx.x >> 5;
    v = wredSum(v);
    if (lane == 0) sbuf[wid] = v;
    __syncthreads();
    if (wid == 0) {
        v = (lane < 8) ? sbuf[lane] : 0.0f;
        v = wredSum(v);
        if (lane == 0) sbuf[0] = v;
    }
    __syncthreads();
    float r = sbuf[0];
    __syncthreads();
    return r;
}

// double block sum (256 threads)
__device__ __forceinline__ double blockSumD(double v, double* dbuf) {
    const int lane = threadIdx.x & 31;
    const int wid  = threadIdx.x >> 5;
#pragma unroll
    for (int o = 16; o; o >>= 1) v += __shfl_down_sync(0xffffffffu, v, o);
    if (lane == 0) dbuf[wid] = v;
    __syncthreads();
    if (wid == 0) {
        v = (lane < 8) ? dbuf[lane] : 0.0;
#pragma unroll
        for (int o = 16; o; o >>= 1) v += __shfl_down_sync(0xffffffffu, v, o);
        if (lane == 0) dbuf[0] = v;
    }
    __syncthreads();
    double r = dbuf[0];
    __syncthreads();
    return r;
}

__device__ __forceinline__ float sqrt_approx(float x) {
    float d; asm("sqrt.approx.f32 %0,%1;" : "=f"(d) : "f"(x)); return d;
}

// ---------------- fused kernel ----------------
// grid (JCHUNKS+1, NB), 256 threads.
//   blockIdx.x <  16 : collapse block (64-col j-window of batch b)
//   blockIdx.x == 16 : stats block of batch b
// Last finishing block runs the finalize reduction and resets g_done.
__global__ __launch_bounds__(CTHREADS) void k_fused(
    const float* __restrict__ pred,
    const float* __restrict__ tru,
    const float* __restrict__ org,
    const float* __restrict__ nfeat,
    float* __restrict__ out, int out_size)
{
    __shared__ float4 sj[CHUNK_J];
    __shared__ float  sred[8];
    __shared__ float  sq[16][8];
    __shared__ double dbuf[8];
    __shared__ bool   amLast;

    const int b  = blockIdx.y;
    const int jc = blockIdx.x;
    const int t  = threadIdx.x;
    const int lane = t & 31;
    const int wid  = t >> 5;

    if (jc < JCHUNKS) {
        // ======================= collapse =======================
        const int jbase = jc * CHUNK_J;
        if (t < CHUNK_J) {
            const int j = jbase + t;
            const float* p = pred + 3 * (size_t)(b * NPG + j);
            const float x = p[0], y = p[1], z = p[2];
            sj[t] = make_float4(x, y, z, fmaf(x, x, fmaf(y, y, z * z)));
        }

        float m2x[4], m2y[4], m2z[4], si[4];
#pragma unroll
        for (int k = 0; k < 4; k++) {
            const int i = t + k * 256;
            const float* p = pred + 3 * (size_t)(b * NPG + i);
            const float x = p[0], y = p[1], z = p[2];
            si[k]  = fmaf(x, x, fmaf(y, y, z * z));
            m2x[k] = -2.0f * x;
            m2y[k] = -2.0f * y;
            m2z[k] = -2.0f * z;
        }
        __syncthreads();

        float acc0 = 0.0f, acc1 = 0.0f, acc2 = 0.0f, acc3 = 0.0f;
#pragma unroll 4
        for (int jj = 0; jj < CHUNK_J; jj++) {
            const float4 q = sj[jj];
#pragma unroll
            for (int k = 0; k < 4; k++) {
                float d2 = fmaf(m2x[k], q.x, fmaf(m2y[k], q.y, fmaf(m2z[k], q.z, si[k] + q.w)));
                d2 = fmaxf(d2, T2CLAMP);
                const float d = sqrt_approx(d2);
                float e = MIN_DIST - d;
                e = fmaxf(e, 0.0f);
                const float c = e * e;
                if (k == 0) acc0 += c; else if (k == 1) acc1 += c;
                else if (k == 2) acc2 += c; else acc3 += c;
            }
        }
        float acc = (acc0 + acc1) + (acc2 + acc3);

        // subtract self-pair (identical arithmetic -> exact cancellation)
#pragma unroll
        for (int k = 0; k < 4; k++) {
            const int i  = t + k * 256;
            const int jj = i - jbase;
            if (jj >= 0 && jj < CHUNK_J) {
                const float4 q = sj[jj];
                float d2 = fmaf(m2x[k], q.x, fmaf(m2y[k], q.y, fmaf(m2z[k], q.z, si[k] + q.w)));
                d2 = fmaxf(d2, T2CLAMP);
                const float d = sqrt_approx(d2);
                float e = MIN_DIST - d;
                e = fmaxf(e, 0.0f);
                acc -= e * e;
            }
        }

        const float S = blockSum(acc, sred);
        if (t == 0) g_coll[b * JCHUNKS + jc] = S;
    } else {
        // ======================= stats =======================
        float px[4], py[4], pz[4], ox[4], oy[4], oz[4];
        float rsum = 0.0f;
#pragma unroll
        for (int k = 0; k < 4; k++) {
            const int idx = b * NPG + t + k * 256;
            const float* pp = pred + 3 * idx;
            const float* tt = tru  + 3 * idx;
            const float* oo = org  + 3 * idx;
            px[k] = pp[0]; py[k] = pp[1]; pz[k] = pp[2];
            const float dx = px[k] - tt[0];
            const float dy = py[k] - tt[1];
            const float dz = pz[k] - tt[2];
            rsum += dx * dx + dy * dy + dz * dz;
            ox[k] = oo[0]; oy[k] = oo[1]; oz[k] = oo[2];
        }

        float lv[14];
        lv[0]  = fminf(fminf(px[0], px[1]), fminf(px[2], px[3]));   // p min x
        lv[1]  = fmaxf(fmaxf(px[0], px[1]), fmaxf(px[2], px[3]));   // p max x
        lv[2]  = fminf(fminf(py[0], py[1]), fminf(py[2], py[3]));
        lv[3]  = fmaxf(fmaxf(py[0], py[1]), fmaxf(py[2], py[3]));
        lv[4]  = fminf(fminf(pz[0], pz[1]), fminf(pz[2], pz[3]));
        lv[5]  = fmaxf(fmaxf(pz[0], pz[1]), fmaxf(pz[2], pz[3]));
        lv[6]  = fminf(fminf(ox[0], ox[1]), fminf(ox[2], ox[3]));
        lv[7]  = fmaxf(fmaxf(ox[0], ox[1]), fmaxf(ox[2], ox[3]));
        lv[8]  = fminf(fminf(oy[0], oy[1]), fminf(oy[2], oy[3]));
        lv[9]  = fmaxf(fmaxf(oy[0], oy[1]), fmaxf(oy[2], oy[3]));
        lv[10] = fminf(fminf(oz[0], oz[1]), fminf(oz[2], oz[3]));
        lv[11] = fmaxf(fmaxf(oz[0], oz[1]), fmaxf(oz[2], oz[3]));
        lv[12] = pz[0] + pz[1] + pz[2] + pz[3];                     // sum pz
        lv[13] = rsum;

        // single parallel warp-reduce pass for all 14 quantities
#pragma unroll
        for (int i = 0; i < 14; i++) {
            float v;
            if (i < 12) v = (i & 1) ? wredMax(lv[i]) : wredMin(lv[i]);
            else        v = wredSum(lv[i]);
            if (lane == 0) sq[i][wid] = v;
        }
        __syncthreads();
        if (t < 14) {
            float a = sq[t][0];
            const bool isMin = (t < 12) && !(t & 1);
            const bool isMax = (t < 12) &&  (t & 1);
#pragma unroll
            for (int w = 1; w < 8; w++) {
                const float u = sq[t][w];
                a = isMin ? fminf(a, u) : (isMax ? fmaxf(a, u) : (a + u));
            }
            sq[t][0] = a;
        }
        __syncthreads();

        const float OMNZ = sq[10][0], OMXZ = sq[11][0];
        const float zr   = __fsub_rn(OMXZ, OMNZ);
        const float thlo = __fadd_rn(OMNZ, __fmul_rn(0.15f, zr));
        const float thhi = __fsub_rn(OMXZ, __fmul_rn(0.15f, zr));

        float esum = 0.0f, ecnt = 0.0f;
#pragma unroll
        for (int k = 0; k < 4; k++) {
            const bool m = (oz[k] <= thlo) || (oz[k] >= thhi);
            if (m) {
                const float dx = px[k] - ox[k];
                const float dy = py[k] - oy[k];
                const float dz = pz[k] - oz[k];
                esum += dx * dx + dy * dy + dz * dz;
                ecnt += 1.0f;
            }
        }
        esum = wredSum(esum);
        ecnt = wredSum(ecnt);
        if (lane == 0) { sq[14][wid] = esum; sq[15][wid] = ecnt; }
        __syncthreads();

        if (t == 0) {
            float ES = 0.0f, EC = 0.0f;
#pragma unroll
            for (int w = 0; w < 8; w++) { ES += sq[14][w]; EC += sq[15][w]; }

            const float pdx = sq[1][0] - sq[0][0];
            const float pdy = sq[3][0] - sq[2][0];
            const float pdz = sq[5][0] - sq[4][0];
            const float odx = sq[7][0] - sq[6][0];
            const float ody = sq[9][0] - sq[8][0];
            const float odz = OMXZ - OMNZ;
            const float rx = (pdx - odx) / (odx + 1e-8f);
            const float ry = (pdy - ody) / (ody + 1e-8f);
            const float rz = (pdz - odz) / (odz + 1e-8f);
            const float xy_pen = fmaxf(rx - 0.02f, 0.0f) + fmaxf(ry - 0.02f, 0.0f);
            const float z_pen  = fmaxf(rz, 0.0f);

            const float zcom  = sq[12][0] * (1.0f / 1024.0f);
            const float znorm = (zcom - sq[4][0]) / ((sq[5][0] - sq[4][0]) + 1e-8f);
            const float v = nfeat[(size_t)b * NPG * NFEA + (NFEA - 3)];
            const float target = (v > 0.0f) ? 0.6f : 0.4f;
            const float dvz = znorm - target;
            const float contrib = (fabsf(v) >= 1e-6f) ? dvz * dvz : 0.0f;

            g_sb[b][0] = sq[13][0];           // rsum
            g_sb[b][1] = ES;
            g_sb[b][2] = EC;
            g_sb[b][3] = xy_pen + 2.0f * z_pen;
            g_sb[b][4] = contrib;
        }
        __syncthreads();
    }

    // ======================= last-block finalize =======================
    __threadfence();
    if (t == 0) {
        const unsigned int ret = atomicAdd(&g_done, 1u);
        amLast = (ret == (unsigned)(NBLOCKS - 1));
    }
    __syncthreads();

    if (amLast) {
        __threadfence();   // acquire: make all partials visible

        double cs = 0.0;
#pragma unroll
        for (int k = 0; k < 4; k++) cs += (double)g_coll[t + k * 256];
        const double COLL = blockSumD(cs, dbuf);

        double r = 0.0, e = 0.0, c = 0.0, vo = 0.0, f = 0.0;
        if (t < NB) {
            r  = (double)g_sb[t][0];
            e  = (double)g_sb[t][1];
            c  = (double)g_sb[t][2];
            vo = (double)g_sb[t][3];
            f  = (double)g_sb[t][4];
        }
        const double RSUM = blockSumD(r,  dbuf);
        const double ESUM = blockSumD(e,  dbuf);
        const double ECNT = blockSumD(c,  dbuf);
        const double VSUM = blockSumD(vo, dbuf);
        const double FSUM = blockSumD(f,  dbuf);

        if (t == 0) {
            const double recon  = RSUM / (double)(NB * NPG * 3);
            const double volume = VSUM / (double)NB;
            const double elec   = ESUM / (ECNT * 3.0);
            const double coll   = COLL / ((double)NB * (double)NPG * (double)(NPG - 1));
            const double field  = FSUM / (double)NB;
            const double total  = 1.0 * recon + 10.0 * volume + 50.0 * elec
                                + 5.0 * coll + 2.0 * field;
            double vals[6] = { total, recon, volume, elec, coll, field };
            for (int i = 0; i < 6 && i < out_size; i++) out[i] = (float)vals[i];
            g_done = 0;   // reset for next graph replay
        }
    }
}

extern "C" void kernel_launch(void* const* d_in, const int* in_sizes, int n_in,
                              void* d_out, int out_size)
{
    // Resolve inputs by element count (robust to metadata ordering).
    int coord_idx[3]; int n_coord = 0;
    int nf_idx = -1, bv_idx = -1;
    for (int i = 0; i < n_in; i++) {
        if (in_sizes[i] == NB * NPG * 3) { if (n_coord < 3) coord_idx[n_coord] = i; n_coord++; }
        else if (in_sizes[i] == NB * NPG * NFEA) nf_idx = i;
        else if (in_sizes[i] == NB * NPG) bv_idx = i;
    }

    const float *pred, *tru, *org, *nf;
    if (n_coord == 3 && nf_idx >= 0) {
        if (bv_idx >= 0 && bv_idx < coord_idx[0]) {
            org  = (const float*)d_in[coord_idx[0]];
            pred = (const float*)d_in[coord_idx[1]];
            tru  = (const float*)d_in[coord_idx[2]];
        } else {
            pred = (const float*)d_in[coord_idx[0]];
            tru  = (const float*)d_in[coord_idx[1]];
            org  = (const float*)d_in[coord_idx[2]];
        }
        nf = (const float*)d_in[nf_idx];
    } else {
        pred = (const float*)d_in[0];
        tru  = (const float*)d_in[1];
        org  = (const float*)d_in[2];
        nf   = (const float*)d_in[3];
    }

    k_fused<<<dim3(JCHUNKS + 1, NB), CTHREADS>>>(pred, tru, org, nf,
                                                 (float*)d_out, out_size);
}

// round 6
// speedup vs baseline: 1.4641x; 1.3315x over previous
#include <cuda_runtime.h>
#include <cstdint>

#define NB   64
#define NPG  1024
#define NFEA 8
#define MIN_DIST 2.9f

#define TILE     128
#define NCHUNK   (NPG / TILE)            // 8
#define NTRI     (NCHUNK * (NCHUNK + 1) / 2)   // 36
#define CTHREADS 256
#define NBLOCKS  ((NTRI + 1) * NB)       // 2368

// triangle tile decode tables (ic >= jc)
__device__ const signed char TIC[NTRI] =
    {0,1,1,2,2,2,3,3,3,3,4,4,4,4,4,5,5,5,5,5,5,
     6,6,6,6,6,6,6,7,7,7,7,7,7,7,7};
__device__ const signed char TJC[NTRI] =
    {0,0,1,0,1,2,0,1,2,3,0,1,2,3,4,0,1,2,3,4,5,
     0,1,2,3,4,5,6,0,1,2,3,4,5,6,7};

// partial slots — fully overwritten every launch
__device__ float g_coll[NTRI * NB];      // weighted tile sums
__device__ float g_sb[NB][8];            // per batch: rsum, esum, ecnt, vol, field
__device__ unsigned int g_done = 0;      // last-block counter (self-resetting)

// ---------------- reduce helpers ----------------
__device__ __forceinline__ float wredSum(float v) {
#pragma unroll
    for (int o = 16; o; o >>= 1) v += __shfl_down_sync(0xffffffffu, v, o);
    return v;
}
__device__ __forceinline__ float wredMin(float v) {
#pragma unroll
    for (int o = 16; o; o >>= 1) v = fminf(v, __shfl_down_sync(0xffffffffu, v, o));
    return v;
}
__device__ __forceinline__ float wredMax(float v) {
#pragma unroll
    for (int o = 16; o; o >>= 1) v = fmaxf(v, __shfl_down_sync(0xffffffffu, v, o));
    return v;
}
__device__ __forceinline__ float blockSum(float v, float* sbuf) {
    const int lane = threadIdx.x & 31;
    const int wid  = threadIdx.x >> 5;
    v = wredSum(v);
    if (lane == 0) sbuf[wid] = v;
    __syncthreads();
    if (wid == 0) {
        v = (lane < 8) ? sbuf[lane] : 0.0f;
        v = wredSum(v);
        if (lane == 0) sbuf[0] = v;
    }
    __syncthreads();
    float r = sbuf[0];
    __syncthreads();
    return r;
}
__device__ __forceinline__ double blockSumD(double v, double* dbuf) {
    const int lane = threadIdx.x & 31;
    const int wid  = threadIdx.x >> 5;
#pragma unroll
    for (int o = 16; o; o >>= 1) v += __shfl_down_sync(0xffffffffu, v, o);
    if (lane == 0) dbuf[wid] = v;
    __syncthreads();
    if (wid == 0) {
        v = (lane < 8) ? dbuf[lane] : 0.0;
#pragma unroll
        for (int o = 16; o; o >>= 1) v += __shfl_down_sync(0xffffffffu, v, o);
        if (lane == 0) dbuf[0] = v;
    }
    __syncthreads();
    double r = dbuf[0];
    __syncthreads();
    return r;
}
__device__ __forceinline__ float sqrt_approx(float x) {
    float d; asm("sqrt.approx.f32 %0,%1;" : "=f"(d) : "f"(x)); return d;
}

// ---------------- fused kernel ----------------
// grid (NTRI+1, NB), 256 threads.
//   blockIdx.x < 36 : collapse triangle tile (ic,jc) of batch b
//   blockIdx.x == 36: stats block of batch b
__global__ __launch_bounds__(CTHREADS) void k_fused(
    const float* __restrict__ pred,
    const float* __restrict__ tru,
    const float* __restrict__ org,
    const float* __restrict__ nfeat,
    float* __restrict__ out, int out_size)
{
    __shared__ float4 sj[TILE];
    __shared__ float  sred[8];
    __shared__ float  sq[16][8];
    __shared__ double dbuf[8];
    __shared__ bool   amLast;

    const int b  = blockIdx.y;
    const int bx = blockIdx.x;
    const int t  = threadIdx.x;
    const int lane = t & 31;
    const int wid  = t >> 5;

    if (bx < NTRI) {
        // ======================= collapse tile =======================
        const int ic = TIC[bx];
        const int jc = TJC[bx];
        const int ibase = b * NPG + ic * TILE;
        const int jbase = b * NPG + jc * TILE;

        if (t < TILE) {
            const float* p = pred + 3 * (size_t)(jbase + t);
            const float x = p[0], y = p[1], z = p[2];
            sj[t] = make_float4(x, y, z, fmaf(x, x, fmaf(y, y, z * z)));
        }

        // own i-point: i_loc = t & 127; j half = t >> 7 (warp-uniform)
        const int i_loc  = t & (TILE - 1);
        const int jhalf  = t >> 7;
        const float* p = pred + 3 * (size_t)(ibase + i_loc);
        const float x = p[0], y = p[1], z = p[2];
        const float si  = fmaf(x, x, fmaf(y, y, z * z));
        const float m2x = -2.0f * x;
        const float m2y = -2.0f * y;
        const float m2z = -2.0f * z;
        __syncthreads();

        float acc0 = 0.0f, acc1 = 0.0f;
#pragma unroll 8
        for (int jj = 0; jj < 64; jj++) {
            const float4 q = sj[jhalf * 64 + jj];
            const float d2 = fmaf(m2x, q.x, fmaf(m2y, q.y, fmaf(m2z, q.z, si + q.w)));
            const float d  = sqrt_approx(d2);            // d2<0 -> NaN -> relu gives 0
            const float e  = fmaxf(MIN_DIST - d, 0.0f);
            if (jj & 1) acc1 = fmaf(e, e, acc1);
            else        acc0 = fmaf(e, e, acc0);
        }
        float acc = acc0 + acc1;

        // diagonal tile: remove the self-pair (identical instruction sequence)
        if (ic == jc) {
            const int jj = i_loc - jhalf * 64;
            if (jj >= 0 && jj < 64) {
                const float4 q = sj[i_loc];
                const float d2 = fmaf(m2x, q.x, fmaf(m2y, q.y, fmaf(m2z, q.z, si + q.w)));
                const float d  = sqrt_approx(d2);
                const float e  = fmaxf(MIN_DIST - d, 0.0f);
                acc = fmaf(-e, e, acc);
            }
        }

        const float S = blockSum(acc, sred);
        if (t == 0) g_coll[b * NTRI + bx] = (ic != jc) ? 2.0f * S : S;  // x2 exact
    } else {
        // ======================= stats =======================
        float px[4], py[4], pz[4], ox[4], oy[4], oz[4];
        float rsum = 0.0f;
#pragma unroll
        for (int k = 0; k < 4; k++) {
            const int idx = b * NPG + t + k * 256;
            const float* pp = pred + 3 * idx;
            const float* tt = tru  + 3 * idx;
            const float* oo = org  + 3 * idx;
            px[k] = pp[0]; py[k] = pp[1]; pz[k] = pp[2];
            const float dx = px[k] - tt[0];
            const float dy = py[k] - tt[1];
            const float dz = pz[k] - tt[2];
            rsum += dx * dx + dy * dy + dz * dz;
            ox[k] = oo[0]; oy[k] = oo[1]; oz[k] = oo[2];
        }

        float lv[14];
        lv[0]  = fminf(fminf(px[0], px[1]), fminf(px[2], px[3]));
        lv[1]  = fmaxf(fmaxf(px[0], px[1]), fmaxf(px[2], px[3]));
        lv[2]  = fminf(fminf(py[0], py[1]), fminf(py[2], py[3]));
        lv[3]  = fmaxf(fmaxf(py[0], py[1]), fmaxf(py[2], py[3]));
        lv[4]  = fminf(fminf(pz[0], pz[1]), fminf(pz[2], pz[3]));
        lv[5]  = fmaxf(fmaxf(pz[0], pz[1]), fmaxf(pz[2], pz[3]));
        lv[6]  = fminf(fminf(ox[0], ox[1]), fminf(ox[2], ox[3]));
        lv[7]  = fmaxf(fmaxf(ox[0], ox[1]), fmaxf(ox[2], ox[3]));
        lv[8]  = fminf(fminf(oy[0], oy[1]), fminf(oy[2], oy[3]));
        lv[9]  = fmaxf(fmaxf(oy[0], oy[1]), fmaxf(oy[2], oy[3]));
        lv[10] = fminf(fminf(oz[0], oz[1]), fminf(oz[2], oz[3]));
        lv[11] = fmaxf(fmaxf(oz[0], oz[1]), fmaxf(oz[2], oz[3]));
        lv[12] = pz[0] + pz[1] + pz[2] + pz[3];
        lv[13] = rsum;

#pragma unroll
        for (int i = 0; i < 14; i++) {
            float v;
            if (i < 12) v = (i & 1) ? wredMax(lv[i]) : wredMin(lv[i]);
            else        v = wredSum(lv[i]);
            if (lane == 0) sq[i][wid] = v;
        }
        __syncthreads();
        if (t < 14) {
            float a = sq[t][0];
            const bool isMin = (t < 12) && !(t & 1);
            const bool isMax = (t < 12) &&  (t & 1);
#pragma unroll
            for (int w = 1; w < 8; w++) {
                const float u = sq[t][w];
                a = isMin ? fminf(a, u) : (isMax ? fmaxf(a, u) : (a + u));
            }
            sq[t][0] = a;
        }
        __syncthreads();

        const float OMNZ = sq[10][0], OMXZ = sq[11][0];
        const float zr   = __fsub_rn(OMXZ, OMNZ);
        const float thlo = __fadd_rn(OMNZ, __fmul_rn(0.15f, zr));
        const float thhi = __fsub_rn(OMXZ, __fmul_rn(0.15f, zr));

        float esum = 0.0f, ecnt = 0.0f;
#pragma unroll
        for (int k = 0; k < 4; k++) {
            const bool m = (oz[k] <= thlo) || (oz[k] >= thhi);
            if (m) {
                const float dx = px[k] - ox[k];
                const float dy = py[k] - oy[k];
                const float dz = pz[k] - oz[k];
                esum += dx * dx + dy * dy + dz * dz;
                ecnt += 1.0f;
            }
        }
        esum = wredSum(esum);
        ecnt = wredSum(ecnt);
        if (lane == 0) { sq[14][wid] = esum; sq[15][wid] = ecnt; }
        __syncthreads();

        if (t == 0) {
            float ES = 0.0f, EC = 0.0f;
#pragma unroll
            for (int w = 0; w < 8; w++) { ES += sq[14][w]; EC += sq[15][w]; }

            const float pdx = sq[1][0] - sq[0][0];
            const float pdy = sq[3][0] - sq[2][0];
            const float pdz = sq[5][0] - sq[4][0];
            const float odx = sq[7][0] - sq[6][0];
            const float ody = sq[9][0] - sq[8][0];
            const float odz = OMXZ - OMNZ;
            const float rx = (pdx - odx) / (odx + 1e-8f);
            const float ry = (pdy - ody) / (ody + 1e-8f);
            const float rz = (pdz - odz) / (odz + 1e-8f);
            const float xy_pen = fmaxf(rx - 0.02f, 0.0f) + fmaxf(ry - 0.02f, 0.0f);
            const float z_pen  = fmaxf(rz, 0.0f);

            const float zcom  = sq[12][0] * (1.0f / 1024.0f);
            const float znorm = (zcom - sq[4][0]) / ((sq[5][0] - sq[4][0]) + 1e-8f);
            const float v = nfeat[(size_t)b * NPG * NFEA + (NFEA - 3)];
            const float target = (v > 0.0f) ? 0.6f : 0.4f;
            const float dvz = znorm - target;
            const float contrib = (fabsf(v) >= 1e-6f) ? dvz * dvz : 0.0f;

            g_sb[b][0] = sq[13][0];
            g_sb[b][1] = ES;
            g_sb[b][2] = EC;
            g_sb[b][3] = xy_pen + 2.0f * z_pen;
            g_sb[b][4] = contrib;
        }
        __syncthreads();
    }

    // ======================= last-block finalize =======================
    __threadfence();
    if (t == 0) {
        const unsigned int ret = atomicAdd(&g_done, 1u);
        amLast = (ret == (unsigned)(NBLOCKS - 1));
    }
    __syncthreads();

    if (amLast) {
        __threadfence();   // acquire

        double cs = 0.0;
#pragma unroll
        for (int k = 0; k < 9; k++) cs += (double)g_coll[t + k * 256];   // 2304 = 9*256
        const double COLL = blockSumD(cs, dbuf);

        double r = 0.0, e = 0.0, c = 0.0, vo = 0.0, f = 0.0;
        if (t < NB) {
            r  = (double)g_sb[t][0];
            e  = (double)g_sb[t][1];
            c  = (double)g_sb[t][2];
            vo = (double)g_sb[t][3];
            f  = (double)g_sb[t][4];
        }
        const double RSUM = blockSumD(r,  dbuf);
        const double ESUM = blockSumD(e,  dbuf);
        const double ECNT = blockSumD(c,  dbuf);
        const double VSUM = blockSumD(vo, dbuf);
        const double FSUM = blockSumD(f,  dbuf);

        if (t == 0) {
            const double recon  = RSUM / (double)(NB * NPG * 3);
            const double volume = VSUM / (double)NB;
            const double elec   = ESUM / (ECNT * 3.0);
            const double coll   = COLL / ((double)NB * (double)NPG * (double)(NPG - 1));
            const double field  = FSUM / (double)NB;
            const double total  = 1.0 * recon + 10.0 * volume + 50.0 * elec
                                + 5.0 * coll + 2.0 * field;
            double vals[6] = { total, recon, volume, elec, coll, field };
            for (int i = 0; i < 6 && i < out_size; i++) out[i] = (float)vals[i];
            g_done = 0;   // reset for next replay
        }
    }
}

extern "C" void kernel_launch(void* const* d_in, const int* in_sizes, int n_in,
                              void* d_out, int out_size)
{
    int coord_idx[3]; int n_coord = 0;
    int nf_idx = -1, bv_idx = -1;
    for (int i = 0; i < n_in; i++) {
        if (in_sizes[i] == NB * NPG * 3) { if (n_coord < 3) coord_idx[n_coord] = i; n_coord++; }
        else if (in_sizes[i] == NB * NPG * NFEA) nf_idx = i;
        else if (in_sizes[i] == NB * NPG) bv_idx = i;
    }

    const float *pred, *tru, *org, *nf;
    if (n_coord == 3 && nf_idx >= 0) {
        if (bv_idx >= 0 && bv_idx < coord_idx[0]) {
            org  = (const float*)d_in[coord_idx[0]];
            pred = (const float*)d_in[coord_idx[1]];
            tru  = (const float*)d_in[coord_idx[2]];
        } else {
            pred = (const float*)d_in[coord_idx[0]];
            tru  = (const float*)d_in[coord_idx[1]];
            org  = (const float*)d_in[coord_idx[2]];
        }
        nf = (const float*)d_in[nf_idx];
    } else {
        pred = (const float*)d_in[0];
        tru  = (const float*)d_in[1];
        org  = (const float*)d_in[2];
        nf   = (const float*)d_in[3];
    }

    k_fused<<<dim3(NTRI + 1, NB), CTHREADS>>>(pred, tru, org, nf,
                                              (float*)d_out, out_size);
}

// round 7
// speedup vs baseline: 1.4786x; 1.0099x over previous
#include <cuda_runtime.h>
#include <cstdint>

#define NB   64
#define NPG  1024
#define NFEA 8
#define MIN_DIST 2.9f

#define TILE     128
#define NCHUNK   (NPG / TILE)                  // 8
#define NTRI     (NCHUNK * (NCHUNK + 1) / 2)   // 36
#define CTHREADS 256
#define NBLOCKS  ((NTRI + 1) * NB)             // 2368
#define JSLICE   16                            // j-cols per thread (128 / 8 warps)

// triangle tile decode tables (ic >= jc)
__device__ const signed char TIC[NTRI] =
    {0,1,1,2,2,2,3,3,3,3,4,4,4,4,4,5,5,5,5,5,5,
     6,6,6,6,6,6,6,7,7,7,7,7,7,7,7};
__device__ const signed char TJC[NTRI] =
    {0,0,1,0,1,2,0,1,2,3,0,1,2,3,4,0,1,2,3,4,5,
     0,1,2,3,4,5,6,0,1,2,3,4,5,6,7};

// partial slots — fully overwritten every launch
__device__ float g_coll[NTRI * NB];      // weighted tile sums
__device__ float g_sb[NB][8];            // per batch: rsum, esum, ecnt, vol, field
__device__ unsigned int g_done = 0;      // last-block counter (self-resetting)

// ---------------- reduce helpers ----------------
__device__ __forceinline__ float wredSum(float v) {
#pragma unroll
    for (int o = 16; o; o >>= 1) v += __shfl_down_sync(0xffffffffu, v, o);
    return v;
}
__device__ __forceinline__ float wredMin(float v) {
#pragma unroll
    for (int o = 16; o; o >>= 1) v = fminf(v, __shfl_down_sync(0xffffffffu, v, o));
    return v;
}
__device__ __forceinline__ float wredMax(float v) {
#pragma unroll
    for (int o = 16; o; o >>= 1) v = fmaxf(v, __shfl_down_sync(0xffffffffu, v, o));
    return v;
}
__device__ __forceinline__ float blockSum(float v, float* sbuf) {
    const int lane = threadIdx.x & 31;
    const int wid  = threadIdx.x >> 5;
    v = wredSum(v);
    if (lane == 0) sbuf[wid] = v;
    __syncthreads();
    if (wid == 0) {
        v = (lane < 8) ? sbuf[lane] : 0.0f;
        v = wredSum(v);
        if (lane == 0) sbuf[0] = v;
    }
    __syncthreads();
    float r = sbuf[0];
    __syncthreads();
    return r;
}
__device__ __forceinline__ double blockSumD(double v, double* dbuf) {
    const int lane = threadIdx.x & 31;
    const int wid  = threadIdx.x >> 5;
#pragma unroll
    for (int o = 16; o; o >>= 1) v += __shfl_down_sync(0xffffffffu, v, o);
    if (lane == 0) dbuf[wid] = v;
    __syncthreads();
    if (wid == 0) {
        v = (lane < 8) ? dbuf[lane] : 0.0;
#pragma unroll
        for (int o = 16; o; o >>= 1) v += __shfl_down_sync(0xffffffffu, v, o);
        if (lane == 0) dbuf[0] = v;
    }
    __syncthreads();
    double r = dbuf[0];
    __syncthreads();
    return r;
}
__device__ __forceinline__ float sqrt_approx(float x) {
    float d; asm("sqrt.approx.f32 %0,%1;" : "=f"(d) : "f"(x)); return d;
}

// ---------------- fused kernel ----------------
// grid (NTRI+1, NB), 256 threads.
//   blockIdx.x < 36 : collapse triangle tile (ic,jc) of batch b
//   blockIdx.x == 36: stats block of batch b
__global__ __launch_bounds__(CTHREADS) void k_fused(
    const float* __restrict__ pred,
    const float* __restrict__ tru,
    const float* __restrict__ org,
    const float* __restrict__ nfeat,
    float* __restrict__ out, int out_size)
{
    __shared__ float4 sj[TILE];
    __shared__ float  sred[8];
    __shared__ float  sq[16][8];
    __shared__ double dbuf[8];
    __shared__ bool   amLast;

    const int b  = blockIdx.y;
    const int bx = blockIdx.x;
    const int t  = threadIdx.x;
    const int lane = t & 31;
    const int wid  = t >> 5;

    if (bx < NTRI) {
        // ======================= collapse tile =======================
        const int ic = TIC[bx];
        const int jc = TJC[bx];
        const int ibase = b * NPG + ic * TILE;
        const int jbase = b * NPG + jc * TILE;

        if (t < TILE) {
            const float* p = pred + 3 * (size_t)(jbase + t);
            const float x = p[0], y = p[1], z = p[2];
            sj[t] = make_float4(x, y, z, fmaf(x, x, fmaf(y, y, z * z)));
        }

        // 4 i-rows per thread: rows r, r+32, r+64, r+96 (r = lane);
        // j-slice per warp: [wid*16, wid*16+16)
        const int r    = lane;
        const int jlo  = wid * JSLICE;

        float m2x[4], m2y[4], m2z[4], si[4];
#pragma unroll
        for (int k = 0; k < 4; k++) {
            const int i = r + 32 * k;
            const float* p = pred + 3 * (size_t)(ibase + i);
            const float x = p[0], y = p[1], z = p[2];
            si[k]  = fmaf(x, x, fmaf(y, y, z * z));
            m2x[k] = -2.0f * x;
            m2y[k] = -2.0f * y;
            m2z[k] = -2.0f * z;
        }
        __syncthreads();

        float acc[4] = {0.0f, 0.0f, 0.0f, 0.0f};
#pragma unroll
        for (int m = 0; m < JSLICE; m++) {
            const float4 q = sj[jlo + m];
#pragma unroll
            for (int k = 0; k < 4; k++) {
                const float d2 = fmaf(m2x[k], q.x,
                                 fmaf(m2y[k], q.y,
                                 fmaf(m2z[k], q.z, si[k] + q.w)));
                const float d  = sqrt_approx(d2);     // d2<0 -> NaN -> relu gives 0
                const float e  = fmaxf(MIN_DIST - d, 0.0f);
                acc[k] = fmaf(e, e, acc[k]);
            }
        }
        float a = (acc[0] + acc[1]) + (acc[2] + acc[3]);

        // diagonal tile: remove self-pairs (identical instruction sequence)
        if (ic == jc) {
#pragma unroll
            for (int k = 0; k < 4; k++) {
                const int i  = r + 32 * k;          // local row == local col for self
                const int jj = i - jlo;
                if (jj >= 0 && jj < JSLICE) {
                    const float4 q = sj[i];
                    const float d2 = fmaf(m2x[k], q.x,
                                     fmaf(m2y[k], q.y,
                                     fmaf(m2z[k], q.z, si[k] + q.w)));
                    const float d  = sqrt_approx(d2);
                    const float e  = fmaxf(MIN_DIST - d, 0.0f);
                    a = fmaf(-e, e, a);
                }
            }
        }

        const float S = blockSum(a, sred);
        if (t == 0) g_coll[b * NTRI + bx] = (ic != jc) ? 2.0f * S : S;  // x2 exact
    } else {
        // ======================= stats =======================
        float px[4], py[4], pz[4], ox[4], oy[4], oz[4];
        float rsum = 0.0f;
#pragma unroll
        for (int k = 0; k < 4; k++) {
            const int idx = b * NPG + t + k * 256;
            const float* pp = pred + 3 * idx;
            const float* tt = tru  + 3 * idx;
            const float* oo = org  + 3 * idx;
            px[k] = pp[0]; py[k] = pp[1]; pz[k] = pp[2];
            const float dx = px[k] - tt[0];
            const float dy = py[k] - tt[1];
            const float dz = pz[k] - tt[2];
            rsum += dx * dx + dy * dy + dz * dz;
            ox[k] = oo[0]; oy[k] = oo[1]; oz[k] = oo[2];
        }

        float lv[14];
        lv[0]  = fminf(fminf(px[0], px[1]), fminf(px[2], px[3]));
        lv[1]  = fmaxf(fmaxf(px[0], px[1]), fmaxf(px[2], px[3]));
        lv[2]  = fminf(fminf(py[0], py[1]), fminf(py[2], py[3]));
        lv[3]  = fmaxf(fmaxf(py[0], py[1]), fmaxf(py[2], py[3]));
        lv[4]  = fminf(fminf(pz[0], pz[1]), fminf(pz[2], pz[3]));
        lv[5]  = fmaxf(fmaxf(pz[0], pz[1]), fmaxf(pz[2], pz[3]));
        lv[6]  = fminf(fminf(ox[0], ox[1]), fminf(ox[2], ox[3]));
        lv[7]  = fmaxf(fmaxf(ox[0], ox[1]), fmaxf(ox[2], ox[3]));
        lv[8]  = fminf(fminf(oy[0], oy[1]), fminf(oy[2], oy[3]));
        lv[9]  = fmaxf(fmaxf(oy[0], oy[1]), fmaxf(oy[2], oy[3]));
        lv[10] = fminf(fminf(oz[0], oz[1]), fminf(oz[2], oz[3]));
        lv[11] = fmaxf(fmaxf(oz[0], oz[1]), fmaxf(oz[2], oz[3]));
        lv[12] = pz[0] + pz[1] + pz[2] + pz[3];
        lv[13] = rsum;

#pragma unroll
        for (int i = 0; i < 14; i++) {
            float v;
            if (i < 12) v = (i & 1) ? wredMax(lv[i]) : wredMin(lv[i]);
            else        v = wredSum(lv[i]);
            if (lane == 0) sq[i][wid] = v;
        }
        __syncthreads();
        if (t < 14) {
            float a = sq[t][0];
            const bool isMin = (t < 12) && !(t & 1);
            const bool isMax = (t < 12) &&  (t & 1);
#pragma unroll
            for (int w = 1; w < 8; w++) {
                const float u = sq[t][w];
                a = isMin ? fminf(a, u) : (isMax ? fmaxf(a, u) : (a + u));
            }
            sq[t][0] = a;
        }
        __syncthreads();

        const float OMNZ = sq[10][0], OMXZ = sq[11][0];
        const float zr   = __fsub_rn(OMXZ, OMNZ);
        const float thlo = __fadd_rn(OMNZ, __fmul_rn(0.15f, zr));
        const float thhi = __fsub_rn(OMXZ, __fmul_rn(0.15f, zr));

        float esum = 0.0f, ecnt = 0.0f;
#pragma unroll
        for (int k = 0; k < 4; k++) {
            const bool m = (oz[k] <= thlo) || (oz[k] >= thhi);
            if (m) {
                const float dx = px[k] - ox[k];
                const float dy = py[k] - oy[k];
                const float dz = pz[k] - oz[k];
                esum += dx * dx + dy * dy + dz * dz;
                ecnt += 1.0f;
            }
        }
        esum = wredSum(esum);
        ecnt = wredSum(ecnt);
        if (lane == 0) { sq[14][wid] = esum; sq[15][wid] = ecnt; }
        __syncthreads();

        if (t == 0) {
            float ES = 0.0f, EC = 0.0f;
#pragma unroll
            for (int w = 0; w < 8; w++) { ES += sq[14][w]; EC += sq[15][w]; }

            const float pdx = sq[1][0] - sq[0][0];
            const float pdy = sq[3][0] - sq[2][0];
            const float pdz = sq[5][0] - sq[4][0];
            const float odx = sq[7][0] - sq[6][0];
            const float ody = sq[9][0] - sq[8][0];
            const float odz = OMXZ - OMNZ;
            const float rx = (pdx - odx) / (odx + 1e-8f);
            const float ry = (pdy - ody) / (ody + 1e-8f);
            const float rz = (pdz - odz) / (odz + 1e-8f);
            const float xy_pen = fmaxf(rx - 0.02f, 0.0f) + fmaxf(ry - 0.02f, 0.0f);
            const float z_pen  = fmaxf(rz, 0.0f);

            const float zcom  = sq[12][0] * (1.0f / 1024.0f);
            const float znorm = (zcom - sq[4][0]) / ((sq[5][0] - sq[4][0]) + 1e-8f);
            const float v = nfeat[(size_t)b * NPG * NFEA + (NFEA - 3)];
            const float target = (v > 0.0f) ? 0.6f : 0.4f;
            const float dvz = znorm - target;
            const float contrib = (fabsf(v) >= 1e-6f) ? dvz * dvz : 0.0f;

            g_sb[b][0] = sq[13][0];
            g_sb[b][1] = ES;
            g_sb[b][2] = EC;
            g_sb[b][3] = xy_pen + 2.0f * z_pen;
            g_sb[b][4] = contrib;
        }
        __syncthreads();
    }

    // ======================= last-block finalize =======================
    __threadfence();
    if (t == 0) {
        const unsigned int ret = atomicAdd(&g_done, 1u);
        amLast = (ret == (unsigned)(NBLOCKS - 1));
    }
    __syncthreads();

    if (amLast) {
        __threadfence();   // acquire

        double cs = 0.0;
#pragma unroll
        for (int k = 0; k < 9; k++) cs += (double)g_coll[t + k * 256];   // 2304 = 9*256
        const double COLL = blockSumD(cs, dbuf);

        double r = 0.0, e = 0.0, c = 0.0, vo = 0.0, f = 0.0;
        if (t < NB) {
            r  = (double)g_sb[t][0];
            e  = (double)g_sb[t][1];
            c  = (double)g_sb[t][2];
            vo = (double)g_sb[t][3];
            f  = (double)g_sb[t][4];
        }
        const double RSUM = blockSumD(r,  dbuf);
        const double ESUM = blockSumD(e,  dbuf);
        const double ECNT = blockSumD(c,  dbuf);
        const double VSUM = blockSumD(vo, dbuf);
        const double FSUM = blockSumD(f,  dbuf);

        if (t == 0) {
            const double recon  = RSUM / (double)(NB * NPG * 3);
            const double volume = VSUM / (double)NB;
            const double elec   = ESUM / (ECNT * 3.0);
            const double coll   = COLL / ((double)NB * (double)NPG * (double)(NPG - 1));
            const double field  = FSUM / (double)NB;
            const double total  = 1.0 * recon + 10.0 * volume + 50.0 * elec
                                + 5.0 * coll + 2.0 * field;
            double vals[6] = { total, recon, volume, elec, coll, field };
            for (int i = 0; i < 6 && i < out_size; i++) out[i] = (float)vals[i];
            g_done = 0;   // reset for next replay
        }
    }
}

extern "C" void kernel_launch(void* const* d_in, const int* in_sizes, int n_in,
                              void* d_out, int out_size)
{
    int coord_idx[3]; int n_coord = 0;
    int nf_idx = -1, bv_idx = -1;
    for (int i = 0; i < n_in; i++) {
        if (in_sizes[i] == NB * NPG * 3) { if (n_coord < 3) coord_idx[n_coord] = i; n_coord++; }
        else if (in_sizes[i] == NB * NPG * NFEA) nf_idx = i;
        else if (in_sizes[i] == NB * NPG) bv_idx = i;
    }

    const float *pred, *tru, *org, *nf;
    if (n_coord == 3 && nf_idx >= 0) {
        if (bv_idx >= 0 && bv_idx < coord_idx[0]) {
            org  = (const float*)d_in[coord_idx[0]];
            pred = (const float*)d_in[coord_idx[1]];
            tru  = (const float*)d_in[coord_idx[2]];
        } else {
            pred = (const float*)d_in[coord_idx[0]];
            tru  = (const float*)d_in[coord_idx[1]];
            org  = (const float*)d_in[coord_idx[2]];
        }
        nf = (const float*)d_in[nf_idx];
    } else {
        pred = (const float*)d_in[0];
        tru  = (const float*)d_in[1];
        org  = (const float*)d_in[2];
        nf   = (const float*)d_in[3];
    }

    k_fused<<<dim3(NTRI + 1, NB), CTHREADS>>>(pred, tru, org, nf,
                                              (float*)d_out, out_size);
}